// round 7
// baseline (speedup 1.0000x reference)
#include <cuda_runtime.h>
#include <math.h>

#define BB 16
#define TT 256
#define SS 1024
#define VV 32000
#define MM (BB*TT)            // 4096 rows in the time-major stream
#define NB_RECUR 128
#define OUT_ELEMS 131072000   // B*T*V

// ---------------- scratch (device globals; no runtime allocation) ----------
// Layout (floats):
//   X0  [4096*1024]
//   Gz  [4096*1024]
//   Gr  [4096*1024]
//   Gn  [4096*1024]
//   H0  [4096*1024]
//   H1  [4096*1024]
//   gh  [16*1024]
//   grh [16*1024]
__device__ __align__(256) float g_scratch[6 * 4194304 + 2 * 16384];
__device__ unsigned int g_bar_count;
__device__ unsigned int g_bar_gen;

// ---------------------------------------------------------------------------
__global__ void embed_kernel(const int* __restrict__ x,
                             const float* __restrict__ emb,
                             float* __restrict__ X0) {
    int row = blockIdx.x;              // row = t*16 + b
    int t = row >> 4, b = row & 15;
    int id = x[b * TT + t];            // x is [B, T]
    const float4* src = (const float4*)(emb + (size_t)id * SS);
    float4* dst = (float4*)(X0 + (size_t)row * SS);
    dst[threadIdx.x] = src[threadIdx.x];   // 256 thr * 4 = 1024
}

__global__ void zero_kernel(float* __restrict__ p, int n) {
    int i = blockIdx.x * blockDim.x + threadIdx.x;
    if (i < n) p[i] = 0.f;
}

// h_final[j][b][s] = Hj[(T-1)*16 + b][s]
__global__ void finalh_kernel(const float* __restrict__ H0,
                              const float* __restrict__ H1,
                              float* __restrict__ out) {
    int i = blockIdx.x * 256 + threadIdx.x;      // 0..32767
    const float* H = (i >> 14) ? H1 : H0;
    out[i] = H[(size_t)(TT - 1) * BB * SS + (i & 16383)];
}

// ---------------------------------------------------------------------------
// fp32 GEMM: C[M,N] = A[M,K] @ B[K,N] + bias[N]
// BM=BN=128, BK=8, 256 threads, 8x8 per thread. M,N,K multiples of 128/8.
// remap!=0: output row m = t*16+b is written to row (b*T + t) of C.
// ---------------------------------------------------------------------------
__global__ __launch_bounds__(256) void gemm128(
    const float* __restrict__ A, const float* __restrict__ Bm,
    const float* __restrict__ bias, float* __restrict__ C,
    int K, int N, int remap)
{
    __shared__ __align__(16) float As[2][8][128];
    __shared__ __align__(16) float Bs[2][8][128];

    int tid = threadIdx.x;
    int m0 = blockIdx.y * 128, n0 = blockIdx.x * 128;

    int ma = tid >> 1, ka = (tid & 1) * 4;     // A: one float4 per thread
    int kb = tid >> 5, nb4 = (tid & 31) * 4;   // B: one float4 per thread
    const float* Ap = A + (size_t)(m0 + ma) * K + ka;
    const float* Bp = Bm + (size_t)kb * N + n0 + nb4;

    float4 pa = *(const float4*)Ap;
    float4 pb = *(const float4*)Bp;
    As[0][ka + 0][ma] = pa.x; As[0][ka + 1][ma] = pa.y;
    As[0][ka + 2][ma] = pa.z; As[0][ka + 3][ma] = pa.w;
    *(float4*)&Bs[0][kb][nb4] = pb;
    __syncthreads();

    float acc[8][8];
#pragma unroll
    for (int i = 0; i < 8; i++)
#pragma unroll
        for (int j = 0; j < 8; j++) acc[i][j] = 0.f;

    int ty = tid >> 4, tx = tid & 15;
    int NT = K >> 3;
    int buf = 0;

    for (int kt = 0; kt < NT; kt++) {
        if (kt + 1 < NT) {
            pa = *(const float4*)(Ap + (kt + 1) * 8);
            pb = *(const float4*)(Bp + (size_t)(kt + 1) * 8 * N);
        }
#pragma unroll
        for (int k = 0; k < 8; k++) {
            float4 a0 = *(const float4*)&As[buf][k][ty * 8];
            float4 a1 = *(const float4*)&As[buf][k][ty * 8 + 4];
            float4 b0 = *(const float4*)&Bs[buf][k][tx * 8];
            float4 b1 = *(const float4*)&Bs[buf][k][tx * 8 + 4];
            float av[8] = {a0.x, a0.y, a0.z, a0.w, a1.x, a1.y, a1.z, a1.w};
            float bv[8] = {b0.x, b0.y, b0.z, b0.w, b1.x, b1.y, b1.z, b1.w};
#pragma unroll
            for (int i = 0; i < 8; i++)
#pragma unroll
                for (int j = 0; j < 8; j++)
                    acc[i][j] = fmaf(av[i], bv[j], acc[i][j]);
        }
        if (kt + 1 < NT) {
            buf ^= 1;
            As[buf][ka + 0][ma] = pa.x; As[buf][ka + 1][ma] = pa.y;
            As[buf][ka + 2][ma] = pa.z; As[buf][ka + 3][ma] = pa.w;
            *(float4*)&Bs[buf][kb][nb4] = pb;
            __syncthreads();
        }
    }

    // epilogue: bias + optional (t,b)->(b,t) remap
#pragma unroll
    for (int i = 0; i < 8; i++) {
        int m = m0 + ty * 8 + i;
        size_t orow = remap ? (size_t)((m & 15) * TT + (m >> 4)) * N
                            : (size_t)m * N;
        int col = n0 + tx * 8;
        float4 o0, o1;
        o0.x = acc[i][0] + bias[col + 0];
        o0.y = acc[i][1] + bias[col + 1];
        o0.z = acc[i][2] + bias[col + 2];
        o0.w = acc[i][3] + bias[col + 3];
        o1.x = acc[i][4] + bias[col + 4];
        o1.y = acc[i][5] + bias[col + 5];
        o1.z = acc[i][6] + bias[col + 6];
        o1.w = acc[i][7] + bias[col + 7];
        *(float4*)(C + orow + col) = o0;
        *(float4*)(C + orow + col + 4) = o1;
    }
}

// ---------------------------------------------------------------------------
// Persistent GRU recurrence for one layer. 128 CTAs x 256 threads.
// CTA owns 8 state columns; U slices (3 x 1024 x 8) resident in SMEM.
// thread -> (c = tid&7, b = (tid>>3)&15, half = tid>>7); k-range 512 per half.
// ---------------------------------------------------------------------------
__device__ __forceinline__ void grid_barrier() {
    __threadfence();
    __syncthreads();
    if (threadIdx.x == 0) {
        unsigned int gen = *((volatile unsigned int*)&g_bar_gen);
        unsigned int a = atomicAdd(&g_bar_count, 1u);
        if (a == NB_RECUR - 1) {
            atomicExch(&g_bar_count, 0u);
            __threadfence();
            atomicAdd(&g_bar_gen, 1u);
        } else {
            while (*((volatile unsigned int*)&g_bar_gen) == gen) {}
        }
    }
    __syncthreads();
}

#define RSTRIDE 1028                      // padded row stride (bank-conflict-free)
#define RECUR_SMEM ((3*8*RSTRIDE + 16*RSTRIDE + 3*128) * 4)

__global__ __launch_bounds__(256) void recur_kernel(
    const float* __restrict__ Gz, const float* __restrict__ Gr,
    const float* __restrict__ Gn,
    const float* __restrict__ Uz, const float* __restrict__ Ur,
    const float* __restrict__ Un,
    float* __restrict__ Hout, float* __restrict__ gh, float* __restrict__ grh)
{
    extern __shared__ float sm[];
    float* suz = sm;                       // [8][RSTRIDE]  (layout [c][k])
    float* sur = suz + 8 * RSTRIDE;
    float* sun = sur + 8 * RSTRIDE;
    float* shs = sun + 8 * RSTRIDE;        // [16][RSTRIDE] h / rh staging
    float* redz = shs + 16 * RSTRIDE;      // [128] partial sums from half=1
    float* redr = redz + 128;
    float* redn = redr + 128;

    int tid = threadIdx.x;
    int c0 = blockIdx.x * 8;

    // one-time weight preload (hidden-part slices, rows k, cols c0..c0+7)
    for (int i = tid; i < 8192; i += 256) {
        int k = i >> 3, c = i & 7;
        suz[c * RSTRIDE + k] = Uz[(size_t)k * SS + c0 + c];
        sur[c * RSTRIDE + k] = Ur[(size_t)k * SS + c0 + c];
        sun[c * RSTRIDE + k] = Un[(size_t)k * SS + c0 + c];
    }
    int c = tid & 7, b = (tid >> 3) & 15, half = tid >> 7;
    int k0 = half << 9;
    __syncthreads();

    for (int t = 0; t < TT; t++) {
        // ---- stage h (L2, bypass stale L1) ----
        for (int i = tid * 4; i < BB * SS; i += 1024) {
            float4 v = __ldcg((const float4*)(gh + i));
            *(float4*)(shs + (i >> 10) * RSTRIDE + (i & 1023)) = v;
        }
        __syncthreads();

        const float* hr  = shs + b * RSTRIDE + k0;
        const float* uzc = suz + c * RSTRIDE + k0;
        const float* urc = sur + c * RSTRIDE + k0;
        float az = 0.f, ar = 0.f;
#pragma unroll 8
        for (int k = 0; k < 512; k += 4) {
            float4 h4 = *(const float4*)(hr + k);
            float4 z4 = *(const float4*)(uzc + k);
            float4 r4 = *(const float4*)(urc + k);
            az = fmaf(h4.x, z4.x, az); az = fmaf(h4.y, z4.y, az);
            az = fmaf(h4.z, z4.z, az); az = fmaf(h4.w, z4.w, az);
            ar = fmaf(h4.x, r4.x, ar); ar = fmaf(h4.y, r4.y, ar);
            ar = fmaf(h4.z, r4.z, ar); ar = fmaf(h4.w, r4.w, ar);
        }
        if (half) { redz[tid - 128] = az; redr[tid - 128] = ar; }
        __syncthreads();

        float zv = 0.f, hv = 0.f;
        if (!half) {
            int gcol = c0 + c;
            size_t grow = (size_t)(t * BB + b) * SS;
            float sz = az + redz[tid] + Gz[grow + gcol];
            float sr = ar + redr[tid] + Gr[grow + gcol];
            zv = 1.f / (1.f + expf(-sz));
            float rv = 1.f / (1.f + expf(-sr));
            hv = shs[b * RSTRIDE + gcol];
            grh[b * SS + gcol] = rv * hv;
        }
        grid_barrier();

        // ---- stage rh ----
        for (int i = tid * 4; i < BB * SS; i += 1024) {
            float4 v = __ldcg((const float4*)(grh + i));
            *(float4*)(shs + (i >> 10) * RSTRIDE + (i & 1023)) = v;
        }
        __syncthreads();

        const float* unc = sun + c * RSTRIDE + k0;
        float an = 0.f;
#pragma unroll 8
        for (int k = 0; k < 512; k += 4) {
            float4 h4 = *(const float4*)(hr + k);
            float4 n4 = *(const float4*)(unc + k);
            an = fmaf(h4.x, n4.x, an); an = fmaf(h4.y, n4.y, an);
            an = fmaf(h4.z, n4.z, an); an = fmaf(h4.w, n4.w, an);
        }
        if (half) redn[tid - 128] = an;
        __syncthreads();

        if (!half) {
            int gcol = c0 + c;
            size_t grow = (size_t)(t * BB + b) * SS;
            float nv = tanhf(an + redn[tid] + Gn[grow + gcol]);
            float hn = (1.f - zv) * hv + zv * nv;
            gh[b * SS + gcol] = hn;
            Hout[grow + gcol] = hn;
        }
        grid_barrier();
    }
}

// ---------------------------------------------------------------------------
extern "C" void kernel_launch(void* const* d_in, const int* in_sizes, int n_in,
                              void* d_out, int out_size) {
    const int*   x   = (const int*)  d_in[0];
    const float* emb = (const float*)d_in[1];
    const float* Wz  = (const float*)d_in[2];
    const float* bz  = (const float*)d_in[3];
    const float* Wr  = (const float*)d_in[4];
    const float* br  = (const float*)d_in[5];
    const float* Wn  = (const float*)d_in[6];
    const float* bn  = (const float*)d_in[7];
    const float* Wo  = (const float*)d_in[8];
    const float* bo  = (const float*)d_in[9];
    float* out = (float*)d_out;

    float* s = nullptr;
    cudaGetSymbolAddress((void**)&s, g_scratch);
    float* X0 = s;
    float* Gz = X0 + 4194304;
    float* Gr = Gz + 4194304;
    float* Gn = Gr + 4194304;
    float* H0 = Gn + 4194304;
    float* H1 = H0 + 4194304;
    float* gh = H1 + 4194304;
    float* grh = gh + 16384;

    cudaFuncSetAttribute(recur_kernel,
                         cudaFuncAttributeMaxDynamicSharedMemorySize, RECUR_SMEM);

    // Wz/Wr/Wn layout: [L][E+S][S]. Input part rows 0..1023; hidden rows 1024..2047.
    const size_t L0_IN  = 0;
    const size_t L0_HID = (size_t)1024 * 1024;
    const size_t L1_IN  = (size_t)2048 * 1024;
    const size_t L1_HID = (size_t)3072 * 1024;

    embed_kernel<<<MM, 256>>>(x, emb, X0);

    dim3 gg(SS / 128, MM / 128);     // gate GEMMs: N=1024
    // layer 0 input projections (bias folded in)
    gemm128<<<gg, 256>>>(X0, Wz + L0_IN, bz,      Gz, SS, SS, 0);
    gemm128<<<gg, 256>>>(X0, Wr + L0_IN, br,      Gr, SS, SS, 0);
    gemm128<<<gg, 256>>>(X0, Wn + L0_IN, bn,      Gn, SS, SS, 0);
    zero_kernel<<<64, 256>>>(gh, BB * SS);
    recur_kernel<<<NB_RECUR, 256, RECUR_SMEM>>>(Gz, Gr, Gn,
        Wz + L0_HID, Wr + L0_HID, Wn + L0_HID, H0, gh, grh);

    // layer 1 input projections from H0
    gemm128<<<gg, 256>>>(H0, Wz + L1_IN, bz + SS, Gz, SS, SS, 0);
    gemm128<<<gg, 256>>>(H0, Wr + L1_IN, br + SS, Gr, SS, SS, 0);
    gemm128<<<gg, 256>>>(H0, Wn + L1_IN, bn + SS, Gn, SS, SS, 0);
    zero_kernel<<<64, 256>>>(gh, BB * SS);
    recur_kernel<<<NB_RECUR, 256, RECUR_SMEM>>>(Gz, Gr, Gn,
        Wz + L1_HID, Wr + L1_HID, Wn + L1_HID, H1, gh, grh);

    // output projection with (t,b)->(b,t) remap
    dim3 go(VV / 128, MM / 128);
    gemm128<<<go, 256>>>(H1, Wo, bo, out, SS, VV, 1);

    if (out_size >= OUT_ELEMS + 2 * BB * SS)
        finalh_kernel<<<128, 256>>>(H0, H1, out + OUT_ELEMS);
}